// round 8
// baseline (speedup 1.0000x reference)
#include <cuda_runtime.h>
#include <cuda_fp16.h>

#define MAXN 100000
#define MAXE 1600000
#define C 64

// ---------------- scratch (static device globals; no allocation) ------------
__device__ int    g_count[MAXN];
__device__ int    g_incl[MAXN + 1024];
__device__ int    g_bsum[128];
__device__ int    g_bpref[128];
__device__ int    g_off[MAXN + 1];
__device__ int    g_cur[MAXN];
__device__ int    g_csr[MAXE];
__device__ float  g_dinv[MAXN];
__device__ float  g_agg[MAXN * C];   // also reused: g_p = g_agg, g_s = g_agg+MAXN
__device__ float  g_h1[MAXN * C];
__device__ float  g_h2[MAXN * C];
__device__ __half g_xh[MAXN * C];    // fp16 copy of gather source (x, then h1)
__device__ __half g_h1h[MAXN * C];

// ---------------- packed f32x2 helpers --------------------------------------
#define FMA2(d, a, b) \
    asm("fma.rn.f32x2 %0, %1, %2, %0;" : "+l"(d) : "l"(a), "l"(b))
#define UNPACK2(lo, hi, v) \
    asm("mov.b64 {%0, %1}, %2;" : "=f"(lo), "=f"(hi) : "l"(v))

// ---------------- CSR build -------------------------------------------------
__global__ void k_zero(int n) {
    int i = blockIdx.x * blockDim.x + threadIdx.x;
    if (i < n) g_count[i] = 0;
}

__global__ void k_hist(const int* __restrict__ row, int e) {
    int i = blockIdx.x * blockDim.x + threadIdx.x;
    if (i < e) atomicAdd(&g_count[row[i]], 1);
}

// block-level inclusive scan (1024 elems/block)
__global__ void k_scan1(int n) {
    __shared__ int sh[1024];
    int t = threadIdx.x;
    int i = blockIdx.x * 1024 + t;
    sh[t] = (i < n) ? g_count[i] : 0;
    __syncthreads();
    #pragma unroll
    for (int off = 1; off < 1024; off <<= 1) {
        int add = (t >= off) ? sh[t - off] : 0;
        __syncthreads();
        sh[t] += add;
        __syncthreads();
    }
    g_incl[i] = sh[t];
    if (t == 1023) g_bsum[blockIdx.x] = sh[1023];
}

// parallel exclusive scan of the <=128 block sums (single block, 128 threads)
__global__ void k_scan2(int nblk) {
    __shared__ int sh[128];
    int t = threadIdx.x;
    sh[t] = (t < nblk) ? g_bsum[t] : 0;
    __syncthreads();
    #pragma unroll
    for (int off = 1; off < 128; off <<= 1) {
        int add = (t >= off) ? sh[t - off] : 0;
        __syncthreads();
        sh[t] += add;
        __syncthreads();
    }
    int incl = sh[t];
    int v = (t < nblk) ? g_bsum[t] : 0;
    if (t < nblk) g_bpref[t] = incl - v;   // exclusive prefix
}

__global__ void k_scan3(int n, int e) {
    int i = blockIdx.x * blockDim.x + threadIdx.x;
    if (i < n) {
        int cnt = g_count[i];
        int off = g_incl[i] - cnt + g_bpref[i >> 10];
        g_off[i]  = off;
        g_cur[i]  = off;
        g_dinv[i] = 1.0f / (float)(cnt > 1 ? cnt : 1);
    }
    if (i == 0) g_off[n] = e;
}

__global__ void k_fill(const int* __restrict__ row, const int* __restrict__ col, int e) {
    int i = blockIdx.x * blockDim.x + threadIdx.x;
    if (i < e) {
        int p = atomicAdd(&g_cur[row[i]], 1);
        g_csr[p] = col[i];
    }
}

// ---------------- fp32 -> fp16 conversion (x -> g_xh) -----------------------
__global__ void k_tohalf(const float* __restrict__ src, int total4) {
    int i = blockIdx.x * blockDim.x + threadIdx.x;   // one float4 per thread
    if (i >= total4) return;
    float4 v = ((const float4*)src)[i];
    __half2 a = __floats2half2_rn(v.x, v.y);
    __half2 b = __floats2half2_rn(v.z, v.w);
    ((uint2*)g_xh)[i] = make_uint2(*(unsigned*)&a, *(unsigned*)&b);
}

// ---------------- mean aggregation (fp16 gather): one warp per node ---------
// srcSel: 0 -> g_xh, 1 -> g_h1h.  Output: g_agg (fp32).
__global__ void k_agg(int srcSel, int n) {
    int w    = (blockIdx.x * blockDim.x + threadIdx.x) >> 5;
    int lane = threadIdx.x & 31;
    if (w >= n) return;
    const __half2* __restrict__ src =
        (const __half2*)((srcSel == 0) ? g_xh : g_h1h);
    int s = g_off[w], e = g_off[w + 1];
    float ax = 0.f, ay = 0.f;
    int j = s;
    for (; j + 3 < e; j += 4) {
        int c0 = g_csr[j], c1 = g_csr[j + 1], c2 = g_csr[j + 2], c3 = g_csr[j + 3];
        float2 v0 = __half22float2(src[c0 * 32 + lane]);
        float2 v1 = __half22float2(src[c1 * 32 + lane]);
        float2 v2 = __half22float2(src[c2 * 32 + lane]);
        float2 v3 = __half22float2(src[c3 * 32 + lane]);
        ax += (v0.x + v1.x) + (v2.x + v3.x);
        ay += (v0.y + v1.y) + (v2.y + v3.y);
    }
    for (; j < e; j++) {
        float2 v = __half22float2(src[g_csr[j] * 32 + lane]);
        ax += v.x; ay += v.y;
    }
    float d = g_dinv[w];
    *(float2*)(g_agg + w * C + (lane << 1)) = make_float2(ax * d, ay * d);
}

// ---------------- GEMM: OUT[n,64] = relu( concat(X, AGG)[n,128] @ W^T + b ) -
// Block tile: 256 nodes x 64 cols, k chunked by 32. Thread tile 8x8 via
// packed f32x2 FFMA: A pairs are adjacent nodes (free from LDS.128 halves),
// B is stored DUPLICATED in smem so a broadcast LDS.128 yields {b,b} pairs.
// If write_half, also emits the fp16 copy (gather source for next layer).
#define NT2 256
#define KC  32

__global__ __launch_bounds__(256) void k_gemm(
    const float* __restrict__ Xin, int srcSel,
    const float* __restrict__ W, const float* __restrict__ B,
    int dstSel, int n, int do_relu, int write_half)
{
    __shared__ float Hs[KC][NT2];      // transposed H chunk: Hs[kk][node]
    __shared__ float Wd[KC][128];      // duplicated W chunk

    const float* __restrict__ Xs = (srcSel == 0) ? Xin : g_h1;
    float* __restrict__ OUT = (dstSel == 1) ? g_h1 : g_h2;

    int t  = threadIdx.x;
    int nb = blockIdx.x * NT2;
    int tx = t & 31;      // node-group: 32 groups x 8 nodes
    int ty = t >> 5;      // col-group:   8 groups x 8 cols

    unsigned long long acc[4][8];
    #pragma unroll
    for (int i = 0; i < 4; i++)
        #pragma unroll
        for (int j = 0; j < 8; j++) acc[i][j] = 0ull;

    int nglob = nb + t;          // H staging: one node per thread
    int colw  = t >> 2;          // W staging: col 0..63
    int q     = t & 3;

    for (int c = 0; c < 4; c++) {
        const float* src = (c < 2) ? Xs : g_agg;
        int koff = (c & 1) * 32;
        int kb   = c * 32;

        const float4* srow = (const float4*)(src + (size_t)nglob * C + koff);
        #pragma unroll
        for (int i = 0; i < 8; i++) {
            float4 v = make_float4(0.f, 0.f, 0.f, 0.f);
            if (nglob < n) v = srow[i];
            int kk = i * 4;
            Hs[kk + 0][t] = v.x;
            Hs[kk + 1][t] = v.y;
            Hs[kk + 2][t] = v.z;
            Hs[kk + 3][t] = v.w;
        }
        #pragma unroll
        for (int i = 0; i < 2; i++) {
            int kk = q * 8 + i * 4;
            float4 wv = *(const float4*)(W + colw * 128 + kb + kk);
            Wd[kk + 0][2 * colw] = wv.x;  Wd[kk + 0][2 * colw + 1] = wv.x;
            Wd[kk + 1][2 * colw] = wv.y;  Wd[kk + 1][2 * colw + 1] = wv.y;
            Wd[kk + 2][2 * colw] = wv.z;  Wd[kk + 2][2 * colw + 1] = wv.z;
            Wd[kk + 3][2 * colw] = wv.w;  Wd[kk + 3][2 * colw + 1] = wv.w;
        }
        __syncthreads();

        #pragma unroll 8
        for (int kk = 0; kk < KC; kk++) {
            ulonglong2 aA = *(const ulonglong2*)&Hs[kk][tx * 8];
            ulonglong2 aB = *(const ulonglong2*)&Hs[kk][tx * 8 + 4];
            const ulonglong2* bp = (const ulonglong2*)&Wd[kk][ty * 16];
            ulonglong2 b01 = bp[0], b23 = bp[1], b45 = bp[2], b67 = bp[3];
            unsigned long long bb[8] = {b01.x, b01.y, b23.x, b23.y,
                                        b45.x, b45.y, b67.x, b67.y};
            #pragma unroll
            for (int j = 0; j < 8; j++) {
                FMA2(acc[0][j], aA.x, bb[j]);
                FMA2(acc[1][j], aA.y, bb[j]);
                FMA2(acc[2][j], aB.x, bb[j]);
                FMA2(acc[3][j], aB.y, bb[j]);
            }
        }
        __syncthreads();
    }

    float4 bb0 = *(const float4*)(B + ty * 8);
    float4 bb1 = *(const float4*)(B + ty * 8 + 4);
    float bias[8] = {bb0.x, bb0.y, bb0.z, bb0.w, bb1.x, bb1.y, bb1.z, bb1.w};

    #pragma unroll
    for (int i2 = 0; i2 < 4; i2++) {
        float lo[8], hi[8];
        #pragma unroll
        for (int j = 0; j < 8; j++) {
            UNPACK2(lo[j], hi[j], acc[i2][j]);
            lo[j] += bias[j]; hi[j] += bias[j];
            if (do_relu) { lo[j] = fmaxf(lo[j], 0.f); hi[j] = fmaxf(hi[j], 0.f); }
        }
        int n0 = nb + tx * 8 + i2 * 2;
        if (n0 < n) {
            float4* o = (float4*)(OUT + (size_t)n0 * C + ty * 8);
            o[0] = make_float4(lo[0], lo[1], lo[2], lo[3]);
            o[1] = make_float4(lo[4], lo[5], lo[6], lo[7]);
            if (write_half) {
                __half2 p0 = __floats2half2_rn(lo[0], lo[1]);
                __half2 p1 = __floats2half2_rn(lo[2], lo[3]);
                __half2 p2 = __floats2half2_rn(lo[4], lo[5]);
                __half2 p3 = __floats2half2_rn(lo[6], lo[7]);
                *(uint4*)(g_h1h + (size_t)n0 * C + ty * 8) =
                    make_uint4(*(unsigned*)&p0, *(unsigned*)&p1,
                               *(unsigned*)&p2, *(unsigned*)&p3);
            }
        }
        if (n0 + 1 < n) {
            float4* o = (float4*)(OUT + (size_t)(n0 + 1) * C + ty * 8);
            o[0] = make_float4(hi[0], hi[1], hi[2], hi[3]);
            o[1] = make_float4(hi[4], hi[5], hi[6], hi[7]);
            if (write_half) {
                __half2 p0 = __floats2half2_rn(hi[0], hi[1]);
                __half2 p1 = __floats2half2_rn(hi[2], hi[3]);
                __half2 p2 = __floats2half2_rn(hi[4], hi[5]);
                __half2 p3 = __floats2half2_rn(hi[6], hi[7]);
                *(uint4*)(g_h1h + (size_t)(n0 + 1) * C + ty * 8) =
                    make_uint4(*(unsigned*)&p0, *(unsigned*)&p1,
                               *(unsigned*)&p2, *(unsigned*)&p3);
            }
        }
    }
}

// ---------------- layer 3 via linearity: agg(h2)@w = agg(h2@w) --------------
__global__ void k_proj(const float* __restrict__ W3, const float* __restrict__ B3, int n) {
    int w    = (blockIdx.x * blockDim.x + threadIdx.x) >> 5;
    int lane = threadIdx.x & 31;
    if (w >= n) return;
    int l2 = lane << 1;
    float2 v  = *(const float2*)(g_h2 + (size_t)w * C + l2);
    float2 ws = *(const float2*)(W3 + l2);
    float2 wa = *(const float2*)(W3 + 64 + l2);
    float s = v.x * ws.x + v.y * ws.y;
    float p = v.x * wa.x + v.y * wa.y;
    #pragma unroll
    for (int o = 16; o; o >>= 1) {
        s += __shfl_xor_sync(0xffffffffu, s, o);
        p += __shfl_xor_sync(0xffffffffu, p, o);
    }
    if (lane == 0) {
        g_agg[MAXN + w] = s + B3[0];   // g_s
        g_agg[w]        = p;           // g_p
    }
}

// scalar aggregation + combine: out[i] = s[i] + dinv[i] * sum p[neighbors]
__global__ void k_out(float* __restrict__ OUT, int n) {
    int i = blockIdx.x * blockDim.x + threadIdx.x;
    if (i >= n) return;
    int s = g_off[i], e = g_off[i + 1];
    float a0 = 0.f, a1 = 0.f, a2 = 0.f, a3 = 0.f;
    int j = s;
    for (; j + 3 < e; j += 4) {
        a0 += g_agg[g_csr[j]];
        a1 += g_agg[g_csr[j + 1]];
        a2 += g_agg[g_csr[j + 2]];
        a3 += g_agg[g_csr[j + 3]];
    }
    for (; j < e; j++) a0 += g_agg[g_csr[j]];
    float acc = (a0 + a1) + (a2 + a3);
    OUT[i] = g_agg[MAXN + i] + acc * g_dinv[i];
}

// ---------------- driver ----------------------------------------------------
extern "C" void kernel_launch(void* const* d_in, const int* in_sizes, int n_in,
                              void* d_out, int out_size)
{
    const float* x  = (const float*)d_in[0];
    const int*   ei = (const int*)  d_in[1];
    const float* W1 = (const float*)d_in[2];
    const float* b1 = (const float*)d_in[3];
    const float* W2 = (const float*)d_in[4];
    const float* b2 = (const float*)d_in[5];
    const float* W3 = (const float*)d_in[6];
    const float* b3 = (const float*)d_in[7];
    float* out = (float*)d_out;

    int n = in_sizes[0] / C;     // 100000
    int e = in_sizes[1] / 2;     // 1600000
    const int* row = ei;
    const int* col = ei + e;

    int nblk = (n + 1023) / 1024;

    // CSR build (reused for all 3 layers) + x->fp16 conversion
    k_zero  <<<(n + 255) / 256, 256>>>(n);
    k_hist  <<<(e + 255) / 256, 256>>>(row, e);
    k_tohalf<<<(n * 16 + 255) / 256, 256>>>(x, n * 16);
    k_scan1 <<<nblk, 1024>>>(n);
    k_scan2 <<<1, 128>>>(nblk);
    k_scan3 <<<(n + 255) / 256, 256>>>(n, e);
    k_fill  <<<(e + 255) / 256, 256>>>(row, col, e);

    int aggBlocks  = (n * 32 + 255) / 256;   // 1 warp per node
    int gemmBlocks = (n + NT2 - 1) / NT2;
    int tpnBlocks  = (n + 255) / 256;        // 1 thread per node

    // layer 1: x -> h1 (agg gathers fp16 x)
    k_agg <<<aggBlocks, 256>>>(0, n);
    k_gemm<<<gemmBlocks, 256>>>(x, 0, W1, b1, /*dst=*/1, n, /*relu=*/1, /*half=*/1);
    // layer 2: h1 -> h2 (agg gathers fp16 h1)
    k_agg <<<aggBlocks, 256>>>(1, n);
    k_gemm<<<gemmBlocks, 256>>>(nullptr, 1, W2, b2, /*dst=*/2, n, /*relu=*/1, /*half=*/0);
    // layer 3 (projected scalars -> scalar aggregation)
    k_proj<<<aggBlocks, 256>>>(W3, b3, n);
    k_out <<<tpnBlocks, 256>>>(out, n);
}

// round 9
// speedup vs baseline: 1.0392x; 1.0392x over previous
#include <cuda_runtime.h>

#define MAXN 100000
#define MAXE 1600000
#define C 64

// ---------------- scratch (static device globals; no allocation) ------------
__device__ int    g_count[MAXN];
__device__ int    g_incl[MAXN + 1024];
__device__ int    g_bsum[128];
__device__ int    g_off[MAXN + 1];
__device__ int    g_cur[MAXN];
__device__ int    g_csr[MAXE];
__device__ float  g_dinv[MAXN];
__device__ float  g_agg[MAXN * C];   // also reused: g_p = g_agg, g_s = g_agg+MAXN
__device__ float  g_h1[MAXN * C];

// ---------------- packed f32x2 helpers --------------------------------------
#define FMA2(d, a, b) \
    asm("fma.rn.f32x2 %0, %1, %2, %0;" : "+l"(d) : "l"(a), "l"(b))
#define UNPACK2(lo, hi, v) \
    asm("mov.b64 {%0, %1}, %2;" : "=f"(lo), "=f"(hi) : "l"(v))

// ---------------- CSR build -------------------------------------------------
__global__ void k_zero(int n) {
    int i = blockIdx.x * blockDim.x + threadIdx.x;
    if (i < n) g_count[i] = 0;
}

__global__ void k_hist(const int* __restrict__ row, int e) {
    int i = blockIdx.x * blockDim.x + threadIdx.x;
    if (i < e) atomicAdd(&g_count[row[i]], 1);
}

// block-level inclusive scan (1024 elems/block)
__global__ void k_scan1(int n) {
    __shared__ int sh[1024];
    int t = threadIdx.x;
    int i = blockIdx.x * 1024 + t;
    sh[t] = (i < n) ? g_count[i] : 0;
    __syncthreads();
    #pragma unroll
    for (int off = 1; off < 1024; off <<= 1) {
        int add = (t >= off) ? sh[t - off] : 0;
        __syncthreads();
        sh[t] += add;
        __syncthreads();
    }
    g_incl[i] = sh[t];
    if (t == 1023) g_bsum[blockIdx.x] = sh[1023];
}

// scan3 with the block-sum prefix folded in (one warp sums <=98 ints).
// blockDim = 256, so every block maps to exactly ONE scan1-block prefix.
__global__ void k_scan3(int n, int e) {
    __shared__ int s_bp;
    int b = (blockIdx.x * 256) >> 10;     // scan1 block id for this block's nodes
    if (threadIdx.x < 32) {
        int acc = 0;
        for (int idx = threadIdx.x; idx < b; idx += 32) acc += g_bsum[idx];
        #pragma unroll
        for (int o = 16; o; o >>= 1) acc += __shfl_xor_sync(0xffffffffu, acc, o);
        if (threadIdx.x == 0) s_bp = acc;
    }
    __syncthreads();
    int i = blockIdx.x * 256 + threadIdx.x;
    if (i < n) {
        int cnt = g_count[i];
        int off = g_incl[i] - cnt + s_bp;
        g_off[i]  = off;
        g_cur[i]  = off;
        g_dinv[i] = 1.0f / (float)(cnt > 1 ? cnt : 1);
    }
    if (i == 0) g_off[n] = e;
}

__global__ void k_fill(const int* __restrict__ row, const int* __restrict__ col, int e) {
    int i = blockIdx.x * blockDim.x + threadIdx.x;
    if (i < e) {
        int p = atomicAdd(&g_cur[row[i]], 1);
        g_csr[p] = col[i];
    }
}

// ---------------- mean aggregation (fp32): one warp per destination node ----
// srcSel: 0 -> external X, 1 -> g_h1.  Output: g_agg.
__global__ void k_agg(const float* __restrict__ Xin, int srcSel, int n) {
    int w    = (blockIdx.x * blockDim.x + threadIdx.x) >> 5;
    int lane = threadIdx.x & 31;
    if (w >= n) return;
    const float* __restrict__ src = (srcSel == 0) ? Xin : g_h1;
    int s = g_off[w], e = g_off[w + 1];
    float ax = 0.f, ay = 0.f;
    int j = s;
    int l2 = lane << 1;
    for (; j + 3 < e; j += 4) {
        int c0 = g_csr[j], c1 = g_csr[j + 1], c2 = g_csr[j + 2], c3 = g_csr[j + 3];
        float2 v0 = *(const float2*)(src + c0 * C + l2);
        float2 v1 = *(const float2*)(src + c1 * C + l2);
        float2 v2 = *(const float2*)(src + c2 * C + l2);
        float2 v3 = *(const float2*)(src + c3 * C + l2);
        ax += (v0.x + v1.x) + (v2.x + v3.x);
        ay += (v0.y + v1.y) + (v2.y + v3.y);
    }
    for (; j < e; j++) {
        int c = g_csr[j];
        float2 v = *(const float2*)(src + c * C + l2);
        ax += v.x; ay += v.y;
    }
    float d = g_dinv[w];
    *(float2*)(g_agg + w * C + l2) = make_float2(ax * d, ay * d);
}

// ---------------- GEMM: relu( concat(X, AGG)[n,128] @ W^T + b ) -------------
// Block tile: 256 nodes x 64 cols, k chunked by 32. Thread tile 8x8 via
// packed f32x2 FFMA. Software-pipelined: next chunk's H+W preloaded into
// registers while FMA-ing the current chunk.
// fuseMode 0: write OUT rows (layer 1 -> g_h1).
// fuseMode 1: layer-3 fusion — never write h2; instead project each node's
//             relu'd row onto W3's two halves and emit g_s/g_p scalars.
#define NT2 256
#define KC  32

__global__ __launch_bounds__(256, 2) void k_gemm(
    const float* __restrict__ Xin, int srcSel,
    const float* __restrict__ W, const float* __restrict__ B,
    int n, int do_relu, int fuseMode, const float* __restrict__ W3)
{
    __shared__ float Hs[KC][NT2];      // transposed H chunk: Hs[kk][node]
    __shared__ float Wd[KC][128];      // duplicated W chunk

    const float* __restrict__ Xs = (srcSel == 0) ? Xin : g_h1;

    int t  = threadIdx.x;
    int nb = blockIdx.x * NT2;
    int tx = t & 31;      // node-group: 32 groups x 8 nodes
    int ty = t >> 5;      // col-group:   8 groups x 8 cols

    unsigned long long acc[4][8];
    #pragma unroll
    for (int i = 0; i < 4; i++)
        #pragma unroll
        for (int j = 0; j < 8; j++) acc[i][j] = 0ull;

    int nglob = nb + t;          // H staging: one node per thread
    int colw  = t >> 2;          // W staging: col 0..63
    int q     = t & 3;

    float4 hreg[8];
    float4 wreg[2];

    // preload chunk 0
    {
        const float* src = Xs;
        const float4* srow = (const float4*)(src + (size_t)nglob * C);
        #pragma unroll
        for (int i = 0; i < 8; i++)
            hreg[i] = (nglob < n) ? srow[i] : make_float4(0.f, 0.f, 0.f, 0.f);
        #pragma unroll
        for (int i = 0; i < 2; i++)
            wreg[i] = *(const float4*)(W + colw * 128 + q * 8 + i * 4);
    }

    for (int c = 0; c < 4; c++) {
        // store staged registers to smem
        #pragma unroll
        for (int i = 0; i < 8; i++) {
            int kk = i * 4;
            Hs[kk + 0][t] = hreg[i].x;
            Hs[kk + 1][t] = hreg[i].y;
            Hs[kk + 2][t] = hreg[i].z;
            Hs[kk + 3][t] = hreg[i].w;
        }
        #pragma unroll
        for (int i = 0; i < 2; i++) {
            int kk = q * 8 + i * 4;
            Wd[kk + 0][2 * colw] = wreg[i].x;  Wd[kk + 0][2 * colw + 1] = wreg[i].x;
            Wd[kk + 1][2 * colw] = wreg[i].y;  Wd[kk + 1][2 * colw + 1] = wreg[i].y;
            Wd[kk + 2][2 * colw] = wreg[i].z;  Wd[kk + 2][2 * colw + 1] = wreg[i].z;
            Wd[kk + 3][2 * colw] = wreg[i].w;  Wd[kk + 3][2 * colw + 1] = wreg[i].w;
        }
        __syncthreads();

        // preload next chunk (independent of the FMA below)
        if (c < 3) {
            int cn = c + 1;
            const float* src = (cn < 2) ? Xs : g_agg;
            int koff = (cn & 1) * 32;
            int kb   = cn * 32;
            const float4* srow = (const float4*)(src + (size_t)nglob * C + koff);
            #pragma unroll
            for (int i = 0; i < 8; i++)
                hreg[i] = (nglob < n) ? srow[i] : make_float4(0.f, 0.f, 0.f, 0.f);
            #pragma unroll
            for (int i = 0; i < 2; i++)
                wreg[i] = *(const float4*)(W + colw * 128 + kb + q * 8 + i * 4);
        }

        #pragma unroll 8
        for (int kk = 0; kk < KC; kk++) {
            ulonglong2 aA = *(const ulonglong2*)&Hs[kk][tx * 8];
            ulonglong2 aB = *(const ulonglong2*)&Hs[kk][tx * 8 + 4];
            const ulonglong2* bp = (const ulonglong2*)&Wd[kk][ty * 16];
            ulonglong2 b01 = bp[0], b23 = bp[1], b45 = bp[2], b67 = bp[3];
            unsigned long long bb[8] = {b01.x, b01.y, b23.x, b23.y,
                                        b45.x, b45.y, b67.x, b67.y};
            #pragma unroll
            for (int j = 0; j < 8; j++) {
                FMA2(acc[0][j], aA.x, bb[j]);
                FMA2(acc[1][j], aA.y, bb[j]);
                FMA2(acc[2][j], aB.x, bb[j]);
                FMA2(acc[3][j], aB.y, bb[j]);
            }
        }
        __syncthreads();
    }

    float4 bb0 = *(const float4*)(B + ty * 8);
    float4 bb1 = *(const float4*)(B + ty * 8 + 4);
    float bias[8] = {bb0.x, bb0.y, bb0.z, bb0.w, bb1.x, bb1.y, bb1.z, bb1.w};

    if (fuseMode == 0) {
        // plain epilogue: write relu rows to g_h1
        #pragma unroll
        for (int i2 = 0; i2 < 4; i2++) {
            float lo[8], hi[8];
            #pragma unroll
            for (int j = 0; j < 8; j++) {
                UNPACK2(lo[j], hi[j], acc[i2][j]);
                lo[j] += bias[j]; hi[j] += bias[j];
                if (do_relu) { lo[j] = fmaxf(lo[j], 0.f); hi[j] = fmaxf(hi[j], 0.f); }
            }
            int n0 = nb + tx * 8 + i2 * 2;
            if (n0 < n) {
                float4* o = (float4*)(g_h1 + (size_t)n0 * C + ty * 8);
                o[0] = make_float4(lo[0], lo[1], lo[2], lo[3]);
                o[1] = make_float4(lo[4], lo[5], lo[6], lo[7]);
            }
            if (n0 + 1 < n) {
                float4* o = (float4*)(g_h1 + (size_t)(n0 + 1) * C + ty * 8);
                o[0] = make_float4(hi[0], hi[1], hi[2], hi[3]);
                o[1] = make_float4(hi[4], hi[5], hi[6], hi[7]);
            }
        }
    } else {
        // layer-3 fusion: project relu'd rows onto W3 halves, reduce the
        // 8 col-groups through smem (reusing Hs storage), emit g_s/g_p.
        float w3s[8], w3p[8];
        #pragma unroll
        for (int j = 0; j < 8; j++) {
            w3s[j] = W3[ty * 8 + j];
            w3p[j] = W3[64 + ty * 8 + j];
        }
        float* Ps = &Hs[0][0];          // [8][256]
        float* Ss = &Hs[0][0] + 2048;   // [8][256]

        #pragma unroll
        for (int i2 = 0; i2 < 4; i2++) {
            float lo[8], hi[8];
            float slo = 0.f, plo = 0.f, shi = 0.f, phi = 0.f;
            #pragma unroll
            for (int j = 0; j < 8; j++) {
                UNPACK2(lo[j], hi[j], acc[i2][j]);
                lo[j] = fmaxf(lo[j] + bias[j], 0.f);
                hi[j] = fmaxf(hi[j] + bias[j], 0.f);
                slo += lo[j] * w3s[j];  plo += lo[j] * w3p[j];
                shi += hi[j] * w3s[j];  phi += hi[j] * w3p[j];
            }
            int nl = tx * 8 + i2 * 2;
            Ss[ty * 256 + nl]     = slo;  Ps[ty * 256 + nl]     = plo;
            Ss[ty * 256 + nl + 1] = shi;  Ps[ty * 256 + nl + 1] = phi;
        }
        __syncthreads();
        int node = nb + t;
        if (node < n) {
            float s = 0.f, p = 0.f;
            #pragma unroll
            for (int g = 0; g < 8; g++) {
                s += Ss[g * 256 + t];
                p += Ps[g * 256 + t];
            }
            g_agg[MAXN + node] = s;   // g_s (bias b3 added in k_out)
            g_agg[node]        = p;   // g_p
        }
    }
}

// scalar aggregation + combine: out[i] = s[i] + b3 + dinv[i] * sum p[nbrs]
__global__ void k_out(float* __restrict__ OUT, const float* __restrict__ B3, int n) {
    int i = blockIdx.x * blockDim.x + threadIdx.x;
    if (i >= n) return;
    int s = g_off[i], e = g_off[i + 1];
    float a0 = 0.f, a1 = 0.f, a2 = 0.f, a3 = 0.f;
    int j = s;
    for (; j + 3 < e; j += 4) {
        a0 += g_agg[g_csr[j]];
        a1 += g_agg[g_csr[j + 1]];
        a2 += g_agg[g_csr[j + 2]];
        a3 += g_agg[g_csr[j + 3]];
    }
    for (; j < e; j++) a0 += g_agg[g_csr[j]];
    float acc = (a0 + a1) + (a2 + a3);
    OUT[i] = g_agg[MAXN + i] + B3[0] + acc * g_dinv[i];
}

// ---------------- driver ----------------------------------------------------
extern "C" void kernel_launch(void* const* d_in, const int* in_sizes, int n_in,
                              void* d_out, int out_size)
{
    const float* x  = (const float*)d_in[0];
    const int*   ei = (const int*)  d_in[1];
    const float* W1 = (const float*)d_in[2];
    const float* b1 = (const float*)d_in[3];
    const float* W2 = (const float*)d_in[4];
    const float* b2 = (const float*)d_in[5];
    const float* W3 = (const float*)d_in[6];
    const float* b3 = (const float*)d_in[7];
    float* out = (float*)d_out;

    int n = in_sizes[0] / C;     // 100000
    int e = in_sizes[1] / 2;     // 1600000
    const int* row = ei;
    const int* col = ei + e;

    int nblk = (n + 1023) / 1024;

    // CSR build (reused for all 3 layers)
    k_zero <<<(n + 255) / 256, 256>>>(n);                  // launch 0
    k_hist <<<(e + 255) / 256, 256>>>(row, e);             // launch 1
    k_scan1<<<nblk, 1024>>>(n);                            // launch 2
    k_scan3<<<(n + 255) / 256, 256>>>(n, e);               // launch 3
    k_fill <<<(e + 255) / 256, 256>>>(row, col, e);        // launch 4

    int aggBlocks  = (n * 32 + 255) / 256;   // 1 warp per node
    int gemmBlocks = (n + NT2 - 1) / NT2;
    int tpnBlocks  = (n + 255) / 256;        // 1 thread per node

    // layer 1: x -> h1        (launch 5 = k_agg: gets profiled by ncu -s 5)
    k_agg <<<aggBlocks, 256>>>(x, 0, n);
    k_gemm<<<gemmBlocks, 256>>>(x, 0, W1, b1, n, 1, /*fuse=*/0, nullptr);
    // layer 2 + 3: h1 -> (s,p) scalars, h2 never materialized
    k_agg <<<aggBlocks, 256>>>(nullptr, 1, n);
    k_gemm<<<gemmBlocks, 256>>>(nullptr, 1, W2, b2, n, 1, /*fuse=*/1, W3);
    // layer 3 scalar aggregation
    k_out <<<tpnBlocks, 256>>>(out, b3, n);
}